// round 16
// baseline (speedup 1.0000x reference)
#include <cuda_runtime.h>
#include <cuda_fp16.h>

typedef unsigned long long u64;
typedef unsigned int uint32;
#define DEV __device__ __forceinline__

// ---------- packed fp32x2 helpers ----------
DEV u64 pack2(float lo, float hi) {
    u64 r; asm("mov.b64 %0, {%1,%2};" : "=l"(r) : "f"(lo), "f"(hi)); return r;
}
DEV void unpack2(u64 v, float& lo, float& hi) {
    asm("mov.b64 {%0,%1}, %2;" : "=f"(lo), "=f"(hi) : "l"(v));
}
DEV u64 ffma2(u64 a, u64 b, u64 c) {
    u64 d; asm("fma.rn.f32x2 %0, %1, %2, %3;" : "=l"(d) : "l"(a), "l"(b), "l"(c)); return d;
}

// ---------- fp16 mma + ldmatrix ----------
DEV void mma16(float4& d, uint32 a0, uint32 a1, uint32 a2, uint32 a3,
               uint32 b0, uint32 b1) {
    asm volatile("mma.sync.aligned.m16n8k16.row.col.f32.f16.f16.f32 "
                 "{%0,%1,%2,%3}, {%4,%5,%6,%7}, {%8,%9}, {%0,%1,%2,%3};"
                 : "+f"(d.x), "+f"(d.y), "+f"(d.z), "+f"(d.w)
                 : "r"(a0), "r"(a1), "r"(a2), "r"(a3), "r"(b0), "r"(b1));
}
DEV void ldsm4(uint32& r0, uint32& r1, uint32& r2, uint32& r3, uint32 addr) {
    asm volatile("ldmatrix.sync.aligned.m8n8.x4.shared.b16 {%0,%1,%2,%3}, [%4];"
                 : "=r"(r0), "=r"(r1), "=r"(r2), "=r"(r3) : "r"(addr));
}
DEV void ldsm2(uint32& r0, uint32& r1, uint32 addr) {
    asm volatile("ldmatrix.sync.aligned.m8n8.x2.shared.b16 {%0,%1}, [%2];"
                 : "=r"(r0), "=r"(r1) : "r"(addr));
}
DEV uint32 smem_u32(const void* p) {
    uint32 a;
    asm("{ .reg .u64 t; cvta.to.shared.u64 t, %1; cvt.u32.u64 %0, t; }"
        : "=r"(a) : "l"(p));
    return a;
}

// ---------- cp.async ----------
#define CP16(dst, src) \
    asm volatile("cp.async.cg.shared.global [%0], [%1], 16;" :: "r"(dst), "l"(src))
#define CP_COMMIT() asm volatile("cp.async.commit_group;" ::: "memory")
#define CP_WAIT0() asm volatile("cp.async.wait_group 0;" ::: "memory")
#define CP_WAIT1() asm volatile("cp.async.wait_group 1;" ::: "memory")
#define CP_WAIT2() asm volatile("cp.async.wait_group 2;" ::: "memory")

#define BATCH 4
#define HW    4096
#define CDIM  512
#define CK    64
#define MROWS (BATCH*HW)

// ---------- device scratch ----------
__device__ __align__(128) __half g_bch[(size_t)MROWS * 256];       // [row][bh|bl|ch|cl]
__device__ __align__(128) __half g_dT[(size_t)BATCH * CDIM * HW];  // d^T fp16

// ===================== fused projection kernel =====================
// interleaved: bid % 5 == 0 -> proj_bc (128 blocks, FFMA2 pipe);
// otherwise   -> dproj (512 blocks, tensor pipe). dynamic smem 47104 B.
#define FP_SMEM 47104

DEV void proj_bc_body(const float* __restrict__ X,
                      const float* __restrict__ Wb,
                      const float* __restrict__ Wc,
                      char* smraw, int bm) {
    float (*As)[132] = (float(*)[132])smraw;
    float (*Bs)[128] = (float(*)[128])(smraw + 8 * 132 * 4);

    int tid = threadIdx.x;
    int tx = tid & 15, ty = tid >> 4;
    int lr = tid >> 1, lc = (tid & 1) * 4;
    int wr = tid >> 5, wc = (tid & 31) * 4;

    u64 acc[8][4];
#pragma unroll
    for (int i = 0; i < 8; i++)
#pragma unroll
        for (int j = 0; j < 4; j++) acc[i][j] = 0ull;

    for (int kk = 0; kk < CDIM; kk += 8) {
        float4 xv = *(const float4*)(X + (size_t)(bm + lr) * CDIM + kk + lc);
        As[lc + 0][lr] = xv.x; As[lc + 1][lr] = xv.y;
        As[lc + 2][lr] = xv.z; As[lc + 3][lr] = xv.w;
        // direct Wb|Wc read (replaces g_wbc packing; identical values)
        if (wc < 64)
            *(float4*)(&Bs[wr][wc]) = *(const float4*)(Wb + (size_t)(kk + wr) * 64 + wc);
        else
            *(float4*)(&Bs[wr][wc]) = *(const float4*)(Wc + (size_t)(kk + wr) * 64 + wc - 64);
        __syncthreads();
#pragma unroll
        for (int k = 0; k < 8; k++) {
            float4 a0 = *(const float4*)(&As[k][ty * 8]);
            float4 a1 = *(const float4*)(&As[k][ty * 8 + 4]);
            float4 b0 = *(const float4*)(&Bs[k][tx * 4]);
            float4 b1 = *(const float4*)(&Bs[k][64 + tx * 4]);
            u64 bp0 = pack2(b0.x, b0.y), bp1 = pack2(b0.z, b0.w);
            u64 bp2 = pack2(b1.x, b1.y), bp3 = pack2(b1.z, b1.w);
            float am[8] = {a0.x, a0.y, a0.z, a0.w, a1.x, a1.y, a1.z, a1.w};
#pragma unroll
            for (int i = 0; i < 8; i++) {
                u64 ap = pack2(am[i], am[i]);
                acc[i][0] = ffma2(ap, bp0, acc[i][0]);
                acc[i][1] = ffma2(ap, bp1, acc[i][1]);
                acc[i][2] = ffma2(ap, bp2, acc[i][2]);
                acc[i][3] = ffma2(ap, bp3, acc[i][3]);
            }
        }
        __syncthreads();
    }
#pragma unroll
    for (int i = 0; i < 8; i++) {
        size_t row = (size_t)(bm + ty * 8 + i);
        __half* rp = g_bch + row * 256;
        float v[8];
        unpack2(acc[i][0], v[0], v[1]); unpack2(acc[i][1], v[2], v[3]);
        unpack2(acc[i][2], v[4], v[5]); unpack2(acc[i][3], v[6], v[7]);
        __half h[8], l[8];
#pragma unroll
        for (int j = 0; j < 8; j++) {
            h[j] = __float2half_rn(v[j]);
            l[j] = __float2half_rn(v[j] - __half2float(h[j]));
        }
        *(__half2*)(rp + tx * 4)           = __halves2half2(h[0], h[1]);
        *(__half2*)(rp + tx * 4 + 2)       = __halves2half2(h[2], h[3]);
        *(__half2*)(rp + 64 + tx * 4)      = __halves2half2(l[0], l[1]);
        *(__half2*)(rp + 64 + tx * 4 + 2)  = __halves2half2(l[2], l[3]);
        *(__half2*)(rp + 128 + tx * 4)     = __halves2half2(h[4], h[5]);
        *(__half2*)(rp + 128 + tx * 4 + 2) = __halves2half2(h[6], h[7]);
        *(__half2*)(rp + 192 + tx * 4)     = __halves2half2(l[4], l[5]);
        *(__half2*)(rp + 192 + tx * 4 + 2) = __halves2half2(l[6], l[7]);
    }
}

DEV void dproj_body(const float* __restrict__ X, const float* __restrict__ Wd,
                    char* smraw, int bm, int bn) {
    __half* Xs = (__half*)smraw;                 // 128*24
    __half* Wt = Xs + 128 * 24;                  // 128*24
    __half* Ts = Wt + 128 * 24;                  // 128*136

    const int tid = threadIdx.x;
    const int lane = tid & 31, w = tid >> 5;
    const int g = lane >> 2, q = lane & 3;
    const int t15 = lane & 15;
    const int mw = (w & 3) * 32, nw = (w >> 2) * 64;

    const uint32 xs_b = smem_u32(Xs);
    const uint32 wt_b = smem_u32(Wt);
    const uint32 aAddr = xs_b + (uint32)((mw + t15) * 48 + ((lane >> 4) & 1) * 16);
    const uint32 bAddr = wt_b + (uint32)((nw + (lane & 7) + ((lane >> 4) & 1) * 8) * 48
                                         + ((lane >> 3) & 1) * 16);

    float4 acc[2][8];
#pragma unroll
    for (int i = 0; i < 2; i++)
#pragma unroll
        for (int j = 0; j < 8; j++) acc[i][j] = make_float4(0.f, 0.f, 0.f, 0.f);

    const int xm = tid >> 1, xk = (tid & 1) * 8;
    const int wk = (tid >> 5) * 2, wn = lane * 4;

    for (int kk = 0; kk < CDIM; kk += 16) {
        {
            const float* src = X + (size_t)(bm + xm) * CDIM + kk + xk;
            float4 v0 = *(const float4*)(src);
            float4 v1 = *(const float4*)(src + 4);
            __half* dst = Xs + xm * 24 + xk;
            *(__half2*)(dst)     = __floats2half2_rn(v0.x, v0.y);
            *(__half2*)(dst + 2) = __floats2half2_rn(v0.z, v0.w);
            *(__half2*)(dst + 4) = __floats2half2_rn(v1.x, v1.y);
            *(__half2*)(dst + 6) = __floats2half2_rn(v1.z, v1.w);
        }
        {
            const float* s0 = Wd + (size_t)(kk + wk) * CDIM + bn + wn;
            const float* s1 = s0 + CDIM;
            float4 a = *(const float4*)s0;
            float4 b = *(const float4*)s1;
            *(__half2*)(Wt + (wn + 0) * 24 + wk) = __floats2half2_rn(a.x, b.x);
            *(__half2*)(Wt + (wn + 1) * 24 + wk) = __floats2half2_rn(a.y, b.y);
            *(__half2*)(Wt + (wn + 2) * 24 + wk) = __floats2half2_rn(a.z, b.z);
            *(__half2*)(Wt + (wn + 3) * 24 + wk) = __floats2half2_rn(a.w, b.w);
        }
        __syncthreads();

        uint32 a0[2][4];
#pragma unroll
        for (int mt = 0; mt < 2; mt++)
            ldsm4(a0[mt][0], a0[mt][1], a0[mt][2], a0[mt][3],
                  aAddr + (uint32)(mt * 16 * 48));
#pragma unroll
        for (int nt2 = 0; nt2 < 4; nt2++) {
            uint32 b0, b1, b2, b3;
            ldsm4(b0, b1, b2, b3, bAddr + (uint32)(nt2 * 16 * 48));
#pragma unroll
            for (int mt = 0; mt < 2; mt++) {
                mma16(acc[mt][nt2 * 2],     a0[mt][0], a0[mt][1], a0[mt][2], a0[mt][3], b0, b1);
                mma16(acc[mt][nt2 * 2 + 1], a0[mt][0], a0[mt][1], a0[mt][2], a0[mt][3], b2, b3);
            }
        }
        __syncthreads();
    }

#pragma unroll
    for (int mt = 0; mt < 2; mt++) {
        int m0 = mw + mt * 16 + g;
#pragma unroll
        for (int nt = 0; nt < 8; nt++) {
            int n0 = nw + nt * 8 + 2 * q;
            Ts[(n0 + 0) * 136 + m0]     = __float2half_rn(acc[mt][nt].x);
            Ts[(n0 + 1) * 136 + m0]     = __float2half_rn(acc[mt][nt].y);
            Ts[(n0 + 0) * 136 + m0 + 8] = __float2half_rn(acc[mt][nt].z);
            Ts[(n0 + 1) * 136 + m0 + 8] = __float2half_rn(acc[mt][nt].w);
        }
    }
    __syncthreads();
    {
        int n = tid >> 1, half = tid & 1;
        int batch = bm >> 12, keyoff = bm & 4095;
        const uint4* src = (const uint4*)(Ts + n * 136 + half * 64);
        uint4* dst = (uint4*)(g_dT + ((size_t)batch * CDIM + bn + n) * HW
                              + keyoff + half * 64);
#pragma unroll
        for (int j = 0; j < 8; j++) dst[j] = src[j];
    }
}

__global__ void __launch_bounds__(256) fatproj(const float* __restrict__ X,
                                               const float* __restrict__ Wb,
                                               const float* __restrict__ Wc,
                                               const float* __restrict__ Wd) {
    extern __shared__ char smraw[];
    int bid = blockIdx.x;
    if (bid % 5 == 0) {
        proj_bc_body(X, Wb, Wc, smraw, (bid / 5) * 128);
    } else {
        int idx = bid - bid / 5 - 1;     // 0..511 contiguous over non-bc blocks
        dproj_body(X, Wd, smraw, (idx & 127) * 128, (idx >> 7) * 128);
    }
}

// ---------- fused flash attention (locked round-9/13 best, unchanged) ----------
#define CS_OFF   0
#define BS_OFF   17408
#define BS_BYTES 34816
#define PS_OFF   87040
#define DS_OFF   104448
#define DS_BYTES 40960
#define STAT_OFF 186368
#define SMEM_FLASH (STAT_OFF + 2560)

__global__ void __launch_bounds__(512, 1) flash16(const float* __restrict__ x,
                                                  const float* __restrict__ gamma,
                                                  float* __restrict__ out) {
    extern __shared__ char sm[];
    __half* Cs = (__half*)(sm + CS_OFF);
    __half* Ps = (__half*)(sm + PS_OFF);
    float* m_part = (float*)(sm + STAT_OFF);        // [4][64]
    float* l_part = m_part + 256;                   // [4][64]
    float* sc_s   = l_part + 256;                   // [64]
    float* l_fin  = sc_s + 64;                      // [64]

    const uint32 smb  = smem_u32(sm);
    const uint32 cs_b = smb + CS_OFF;
    const uint32 bs_b = smb + BS_OFF;
    const uint32 ps_b = smb + PS_OFF;
    const uint32 ds_b = smb + DS_OFF;

    const int tid = threadIdx.x;
    const int wid = tid >> 5, lane = tid & 31;
    const int g = lane >> 2, q = lane & 3;
    const int qg = wid & 3;          // S: q-group rows qg*16..+15
    const int kq = wid >> 2;         // S: key-quarter (32k)
    const int qsub = wid & 1;        // PV: q-half (32 rows)
    const int fgrp = wid >> 1;       // PV: f-group (64 cols)
    const int t15 = lane & 15;
    const int qb = blockIdx.x * 64;
    const int bz = blockIdx.y;
    const int rowbase = bz * HW;

    // ---- load Cs once (ch|cl) ----
    {
        int r = tid >> 3, c = tid & 7;
        const uint4* src = (const uint4*)(g_bch + (size_t)(rowbase + qb + r) * 256 + 128);
        *(uint4*)(Cs + r * 136 + c * 8)       = src[c];
        *(uint4*)(Cs + r * 136 + (c + 8) * 8) = src[c + 8];
    }

    float4 oacc[16];
#pragma unroll
    for (int i = 0; i < 16; i++) oacc[i] = make_float4(0.f, 0.f, 0.f, 0.f);
    float mrun0 = -1e30f, mrun1 = -1e30f;
    float lrun0 = 0.f, lrun1 = 0.f;

    const uint32 aCh  = cs_b + (uint32)((qg * 16 + t15) * 272 + ((lane >> 4) & 1) * 16);
    const uint32 bBh0 = bs_b + (uint32)((kq * 32 + (lane & 7)) * 272 + ((lane >> 3) & 1) * 16);
    const uint32 psA  = ps_b + (uint32)((qsub * 32 + t15) * 272 + ((lane >> 4) & 1) * 16);
    const uint32 dRow = ds_b + (uint32)((fgrp * 64 + (lane & 7) + ((lane >> 4) & 1) * 8) * 80
                                        + ((lane >> 3) & 1) * 16);
    const int r0row = qg * 16 + g;            // S stat rows
    const int pvrow = qsub * 32 + g;          // PV rows

    const __half* dsrc = g_dT + ((size_t)(bz * CDIM + tid)) * HW;
    const uint32 dsDst = ds_b + (uint32)(tid * 80);
    const int bsR = tid >> 2, bsC = tid & 3;
    const uint32 bsDst = bs_b + (uint32)(bsR * 272 + bsC * 16);

    // prefetch Bs tile 0
    {
        const __half* src = g_bch + (size_t)(rowbase + bsR) * 256 + bsC * 8;
#pragma unroll
        for (int j = 0; j < 4; j++) CP16(bsDst + j * 64, src + j * 32);
        CP_COMMIT();
    }

    for (int t = 0; t < 32; t++) {
        const int kt = t * 128;
        const uint32 bsBuf = (uint32)((t & 1) * BS_BYTES);

        // issue Ds chunks 0,1
#pragma unroll
        for (int c = 0; c < 2; c++) {
            const __half* src = dsrc + kt + c * 32;
            uint32 dst = dsDst + (uint32)(c * DS_BYTES);
#pragma unroll
            for (int j = 0; j < 4; j++) CP16(dst + j * 16, src + j * 8);
            CP_COMMIT();
        }
        CP_WAIT2();          // Bs(t) done
        __syncthreads();

        // ---- S phase: single fp32 accumulator, prefetched fragments ----
        float4 sacc[4];
#pragma unroll
        for (int i = 0; i < 4; i++) sacc[i] = make_float4(0.f, 0.f, 0.f, 0.f);
        const uint32 bB = bBh0 + bsBuf;
        {
            uint32 ah[4], al[4], nah[4], nal[4];
            uint32 bh0, bh1, bl0, bl1, nbh0, nbh1, nbl0, nbl1;
            ldsm4(ah[0], ah[1], ah[2], ah[3], aCh);
            ldsm4(al[0], al[1], al[2], al[3], aCh + 128);
            ldsm2(bh0, bh1, bB);
            ldsm2(bl0, bl1, bB + 128);
#pragma unroll
            for (int ec = 0; ec < 4; ec++) {
                if (ec < 3) {
                    ldsm4(nah[0], nah[1], nah[2], nah[3], aCh + (ec + 1) * 32);
                    ldsm4(nal[0], nal[1], nal[2], nal[3], aCh + (ec + 1) * 32 + 128);
                }
#pragma unroll
                for (int nt = 0; nt < 4; nt++) {
                    if (nt < 3) {
                        ldsm2(nbh0, nbh1, bB + (nt + 1) * 2176 + ec * 32);
                        ldsm2(nbl0, nbl1, bB + (nt + 1) * 2176 + ec * 32 + 128);
                    } else if (ec < 3) {
                        ldsm2(nbh0, nbh1, bB + (ec + 1) * 32);
                        ldsm2(nbl0, nbl1, bB + (ec + 1) * 32 + 128);
                    }
                    mma16(sacc[nt], ah[0], ah[1], ah[2], ah[3], bh0, bh1);
                    mma16(sacc[nt], al[0], al[1], al[2], al[3], bh0, bh1);
                    mma16(sacc[nt], ah[0], ah[1], ah[2], ah[3], bl0, bl1);
                    bh0 = nbh0; bh1 = nbh1; bl0 = nbl0; bl1 = nbl1;
                }
#pragma unroll
                for (int j = 0; j < 4; j++) { ah[j] = nah[j]; al[j] = nal[j]; }
            }
        }

        // ---- softmax partials ----
        float mx0 = sacc[0].x, mx1 = sacc[0].z;
#pragma unroll
        for (int nt = 0; nt < 4; nt++) {
            mx0 = fmaxf(mx0, fmaxf(sacc[nt].x, sacc[nt].y));
            mx1 = fmaxf(mx1, fmaxf(sacc[nt].z, sacc[nt].w));
        }
        mx0 = fmaxf(mx0, __shfl_xor_sync(0xffffffffu, mx0, 1));
        mx0 = fmaxf(mx0, __shfl_xor_sync(0xffffffffu, mx0, 2));
        mx1 = fmaxf(mx1, __shfl_xor_sync(0xffffffffu, mx1, 1));
        mx1 = fmaxf(mx1, __shfl_xor_sync(0xffffffffu, mx1, 2));
        if (q == 0) {
            m_part[kq * 64 + r0row]     = mx0;
            m_part[kq * 64 + r0row + 8] = mx1;
        }
        __syncthreads();

        float mt0 = fmaxf(fmaxf(m_part[r0row], m_part[64 + r0row]),
                          fmaxf(m_part[128 + r0row], m_part[192 + r0row]));
        float mt1 = fmaxf(fmaxf(m_part[r0row + 8], m_part[64 + r0row + 8]),
                          fmaxf(m_part[128 + r0row + 8], m_part[192 + r0row + 8]));
        float mn0 = fmaxf(mrun0, mt0), mn1 = fmaxf(mrun1, mt1);
        float sc0 = __expf(mrun0 - mn0), sc1 = __expf(mrun1 - mn1);
        mrun0 = mn0; mrun1 = mn1;

        float ls0 = 0.f, ls1 = 0.f;
#pragma unroll
        for (int nt = 0; nt < 4; nt++) {
            float px = __expf(sacc[nt].x - mn0), py = __expf(sacc[nt].y - mn0);
            float pz = __expf(sacc[nt].z - mn1), pw = __expf(sacc[nt].w - mn1);
            ls0 += px + py; ls1 += pz + pw;
            int col = kq * 32 + nt * 8 + 2 * q;
            *(__half2*)(Ps + r0row * 136 + col)       = __floats2half2_rn(px, py);
            *(__half2*)(Ps + (r0row + 8) * 136 + col) = __floats2half2_rn(pz, pw);
        }
        ls0 += __shfl_xor_sync(0xffffffffu, ls0, 1);
        ls0 += __shfl_xor_sync(0xffffffffu, ls0, 2);
        ls1 += __shfl_xor_sync(0xffffffffu, ls1, 1);
        ls1 += __shfl_xor_sync(0xffffffffu, ls1, 2);
        if (q == 0) {
            l_part[kq * 64 + r0row]     = ls0;
            l_part[kq * 64 + r0row + 8] = ls1;
            if (kq == 0) { sc_s[r0row] = sc0; sc_s[r0row + 8] = sc1; }
        }

        // prefetch next Bs tile (empty group on last tile keeps counts exact)
        if (t < 31) {
            const __half* src = g_bch + (size_t)(rowbase + kt + 128 + bsR) * 256 + bsC * 8;
            uint32 dst = bsDst + (uint32)(((t + 1) & 1) * BS_BYTES);
#pragma unroll
            for (int j = 0; j < 4; j++) CP16(dst + j * 64, src + j * 32);
        }
        CP_COMMIT();
        __syncthreads();

        // ---- rescale O only when max moved ----
        {
            float s0 = sc_s[pvrow], s1 = sc_s[pvrow + 8];
            float s2 = sc_s[pvrow + 16], s3 = sc_s[pvrow + 24];
            bool noscale = __all_sync(0xffffffffu,
                (s0 == 1.f) && (s1 == 1.f) && (s2 == 1.f) && (s3 == 1.f));
            if (!noscale) {
#pragma unroll
                for (int nt = 0; nt < 8; nt++) {
                    oacc[nt].x *= s0; oacc[nt].y *= s0;
                    oacc[nt].z *= s1; oacc[nt].w *= s1;
                    oacc[8 + nt].x *= s2; oacc[8 + nt].y *= s2;
                    oacc[8 + nt].z *= s3; oacc[8 + nt].w *= s3;
                }
            }
        }
        lrun0 = lrun0 * sc0 + (l_part[r0row] + l_part[64 + r0row]
                             + l_part[128 + r0row] + l_part[192 + r0row]);
        lrun1 = lrun1 * sc1 + (l_part[r0row + 8] + l_part[64 + r0row + 8]
                             + l_part[128 + r0row + 8] + l_part[192 + r0row + 8]);

        // ---- PV: 4 chunks of 32 keys, cp.async pipelined + fragment prefetch ----
#pragma unroll
        for (int c = 0; c < 4; c++) {
            if (c == 0) CP_WAIT2();
            else if (c == 1) CP_WAIT2();
            else if (c == 2) CP_WAIT1();
            else CP_WAIT0();
            __syncthreads();
            const uint32 dBuf = (uint32)((c & 1) * DS_BYTES);
            uint32 pa[4], pb[4], npa[4], npb[4], bf[4], nbf[4];
            ldsm4(pa[0], pa[1], pa[2], pa[3], psA + (uint32)(c * 64));
            ldsm4(pb[0], pb[1], pb[2], pb[3], psA + 16 * 272 + (uint32)(c * 64));
            ldsm4(bf[0], bf[1], bf[2], bf[3], dRow + dBuf);
#pragma unroll
            for (int kcl = 0; kcl < 2; kcl++) {
#pragma unroll
                for (int ftp = 0; ftp < 4; ftp++) {
                    if (ftp < 3) {
                        ldsm4(nbf[0], nbf[1], nbf[2], nbf[3],
                              dRow + dBuf + (uint32)((ftp + 1) * 1280 + kcl * 32));
                    } else if (kcl == 0) {
                        ldsm4(npa[0], npa[1], npa[2], npa[3], psA + (uint32)(c * 64 + 32));
                        ldsm4(npb[0], npb[1], npb[2], npb[3],
                              psA + 16 * 272 + (uint32)(c * 64 + 32));
                        ldsm4(nbf[0], nbf[1], nbf[2], nbf[3], dRow + dBuf + 32);
                    }
                    mma16(oacc[ftp * 2],     pa[0], pa[1], pa[2], pa[3], bf[0], bf[1]);
                    mma16(oacc[ftp * 2 + 1], pa[0], pa[1], pa[2], pa[3], bf[2], bf[3]);
                    mma16(oacc[8 + ftp * 2],     pb[0], pb[1], pb[2], pb[3], bf[0], bf[1]);
                    mma16(oacc[8 + ftp * 2 + 1], pb[0], pb[1], pb[2], pb[3], bf[2], bf[3]);
#pragma unroll
                    for (int j = 0; j < 4; j++) bf[j] = nbf[j];
                    if (ftp == 3 && kcl == 0) {
#pragma unroll
                        for (int j = 0; j < 4; j++) { pa[j] = npa[j]; pb[j] = npb[j]; }
                    }
                }
            }
            __syncthreads();
            if (c < 2) {
                const __half* src = dsrc + kt + (c + 2) * 32;
                uint32 dst = dsDst + dBuf;
#pragma unroll
                for (int j = 0; j < 4; j++) CP16(dst + j * 16, src + j * 8);
                CP_COMMIT();
            }
        }
    }

    // ---- publish final l, epilogue ----
    if (kq == 0 && q == 0) {
        l_fin[r0row]     = lrun0;
        l_fin[r0row + 8] = lrun1;
    }
    __syncthreads();
    {
        float li0 = 1.0f / l_fin[pvrow],      li1 = 1.0f / l_fin[pvrow + 8];
        float li2 = 1.0f / l_fin[pvrow + 16], li3 = 1.0f / l_fin[pvrow + 24];
        float gam = *gamma;
#pragma unroll
        for (int sub = 0; sub < 2; sub++) {
            size_t row0 = (size_t)(rowbase + qb + pvrow + sub * 16);
            size_t row1 = row0 + 8;
            float a0 = sub ? li2 : li0, a1 = sub ? li3 : li1;
#pragma unroll
            for (int nt = 0; nt < 8; nt++) {
                int col = fgrp * 64 + nt * 8 + 2 * q;
                float4 o = oacc[sub * 8 + nt];
                float2 x0 = *(const float2*)(x + row0 * CDIM + col);
                float2 x1 = *(const float2*)(x + row1 * CDIM + col);
                *(float2*)(out + row0 * CDIM + col) =
                    make_float2(gam * o.x * a0 + x0.x, gam * o.y * a0 + x0.y);
                *(float2*)(out + row1 * CDIM + col) =
                    make_float2(gam * o.z * a1 + x1.x, gam * o.w * a1 + x1.y);
            }
        }
    }
}

// ---------- launch ----------
extern "C" void kernel_launch(void* const* d_in, const int* in_sizes, int n_in,
                              void* d_out, int out_size) {
    const float* x     = (const float*)d_in[0];
    const float* Wb    = (const float*)d_in[1];
    const float* Wc    = (const float*)d_in[2];
    const float* Wd    = (const float*)d_in[3];
    const float* gamma = (const float*)d_in[4];
    float* out = (float*)d_out;

    cudaFuncSetAttribute(fatproj, cudaFuncAttributeMaxDynamicSharedMemorySize, FP_SMEM);
    fatproj<<<640, 256, FP_SMEM>>>(x, Wb, Wc, Wd);

    cudaFuncSetAttribute(flash16, cudaFuncAttributeMaxDynamicSharedMemorySize,
                         (int)SMEM_FLASH);
    flash16<<<dim3(HW / 64, BATCH), 512, SMEM_FLASH>>>(x, gamma, out);
}

// round 17
// speedup vs baseline: 1.0839x; 1.0839x over previous
#include <cuda_runtime.h>
#include <cuda_fp16.h>

typedef unsigned long long u64;
typedef unsigned int uint32;
#define DEV __device__ __forceinline__

// ---------- packed fp32x2 helpers ----------
DEV u64 pack2(float lo, float hi) {
    u64 r; asm("mov.b64 %0, {%1,%2};" : "=l"(r) : "f"(lo), "f"(hi)); return r;
}
DEV void unpack2(u64 v, float& lo, float& hi) {
    asm("mov.b64 {%0,%1}, %2;" : "=f"(lo), "=f"(hi) : "l"(v));
}
DEV u64 ffma2(u64 a, u64 b, u64 c) {
    u64 d; asm("fma.rn.f32x2 %0, %1, %2, %3;" : "=l"(d) : "l"(a), "l"(b), "l"(c)); return d;
}

// ---------- fp16 mma + ldmatrix ----------
DEV void mma16(float4& d, uint32 a0, uint32 a1, uint32 a2, uint32 a3,
               uint32 b0, uint32 b1) {
    asm volatile("mma.sync.aligned.m16n8k16.row.col.f32.f16.f16.f32 "
                 "{%0,%1,%2,%3}, {%4,%5,%6,%7}, {%8,%9}, {%0,%1,%2,%3};"
                 : "+f"(d.x), "+f"(d.y), "+f"(d.z), "+f"(d.w)
                 : "r"(a0), "r"(a1), "r"(a2), "r"(a3), "r"(b0), "r"(b1));
}
DEV void ldsm4(uint32& r0, uint32& r1, uint32& r2, uint32& r3, uint32 addr) {
    asm volatile("ldmatrix.sync.aligned.m8n8.x4.shared.b16 {%0,%1,%2,%3}, [%4];"
                 : "=r"(r0), "=r"(r1), "=r"(r2), "=r"(r3) : "r"(addr));
}
DEV void ldsm2(uint32& r0, uint32& r1, uint32 addr) {
    asm volatile("ldmatrix.sync.aligned.m8n8.x2.shared.b16 {%0,%1}, [%2];"
                 : "=r"(r0), "=r"(r1) : "r"(addr));
}
DEV uint32 smem_u32(const void* p) {
    uint32 a;
    asm("{ .reg .u64 t; cvta.to.shared.u64 t, %1; cvt.u32.u64 %0, t; }"
        : "=r"(a) : "l"(p));
    return a;
}

// ---------- cp.async ----------
#define CP16(dst, src) \
    asm volatile("cp.async.cg.shared.global [%0], [%1], 16;" :: "r"(dst), "l"(src))
#define CP_COMMIT() asm volatile("cp.async.commit_group;" ::: "memory")
#define CP_WAIT0() asm volatile("cp.async.wait_group 0;" ::: "memory")
#define CP_WAIT1() asm volatile("cp.async.wait_group 1;" ::: "memory")
#define CP_WAIT2() asm volatile("cp.async.wait_group 2;" ::: "memory")

#define BATCH 4
#define HW    4096
#define CDIM  512
#define CK    64
#define MROWS (BATCH*HW)

// ---------- device scratch ----------
__device__ __align__(128) float  g_wbc[CDIM * 128];
__device__ __align__(128) __half g_bch[(size_t)MROWS * 256];       // [row][bh|bl|ch|cl]
__device__ __align__(128) __half g_dT[(size_t)BATCH * CDIM * HW];  // d^T fp16

// ---------- pack Wb|Wc ----------
__global__ void pack_wbc(const float* __restrict__ Wb, const float* __restrict__ Wc) {
    int i = blockIdx.x * 256 + threadIdx.x;
    if (i < CDIM * CK) {
        int k = i / CK, n = i % CK;
        g_wbc[k * 128 + n]      = Wb[i];
        g_wbc[k * 128 + 64 + n] = Wc[i];
    }
}

// ===================== fused projection kernel (round-15 segregated) =====================
#define FP_SMEM 47104

DEV void proj_bc_body(const float* __restrict__ X, char* smraw, int bm) {
    float (*As)[132] = (float(*)[132])smraw;
    float (*Bs)[128] = (float(*)[128])(smraw + 8 * 132 * 4);

    int tid = threadIdx.x;
    int tx = tid & 15, ty = tid >> 4;
    int lr = tid >> 1, lc = (tid & 1) * 4;
    int wr = tid >> 5, wc = (tid & 31) * 4;

    u64 acc[8][4];
#pragma unroll
    for (int i = 0; i < 8; i++)
#pragma unroll
        for (int j = 0; j < 4; j++) acc[i][j] = 0ull;

    for (int kk = 0; kk < CDIM; kk += 8) {
        float4 xv = *(const float4*)(X + (size_t)(bm + lr) * CDIM + kk + lc);
        As[lc + 0][lr] = xv.x; As[lc + 1][lr] = xv.y;
        As[lc + 2][lr] = xv.z; As[lc + 3][lr] = xv.w;
        *(float4*)(&Bs[wr][wc]) = *(const float4*)(g_wbc + (size_t)(kk + wr) * 128 + wc);
        __syncthreads();
#pragma unroll
        for (int k = 0; k < 8; k++) {
            float4 a0 = *(const float4*)(&As[k][ty * 8]);
            float4 a1 = *(const float4*)(&As[k][ty * 8 + 4]);
            float4 b0 = *(const float4*)(&Bs[k][tx * 4]);
            float4 b1 = *(const float4*)(&Bs[k][64 + tx * 4]);
            u64 bp0 = pack2(b0.x, b0.y), bp1 = pack2(b0.z, b0.w);
            u64 bp2 = pack2(b1.x, b1.y), bp3 = pack2(b1.z, b1.w);
            float am[8] = {a0.x, a0.y, a0.z, a0.w, a1.x, a1.y, a1.z, a1.w};
#pragma unroll
            for (int i = 0; i < 8; i++) {
                u64 ap = pack2(am[i], am[i]);
                acc[i][0] = ffma2(ap, bp0, acc[i][0]);
                acc[i][1] = ffma2(ap, bp1, acc[i][1]);
                acc[i][2] = ffma2(ap, bp2, acc[i][2]);
                acc[i][3] = ffma2(ap, bp3, acc[i][3]);
            }
        }
        __syncthreads();
    }
#pragma unroll
    for (int i = 0; i < 8; i++) {
        size_t row = (size_t)(bm + ty * 8 + i);
        __half* rp = g_bch + row * 256;
        float v[8];
        unpack2(acc[i][0], v[0], v[1]); unpack2(acc[i][1], v[2], v[3]);
        unpack2(acc[i][2], v[4], v[5]); unpack2(acc[i][3], v[6], v[7]);
        __half h[8], l[8];
#pragma unroll
        for (int j = 0; j < 8; j++) {
            h[j] = __float2half_rn(v[j]);
            l[j] = __float2half_rn(v[j] - __half2float(h[j]));
        }
        *(__half2*)(rp + tx * 4)           = __halves2half2(h[0], h[1]);
        *(__half2*)(rp + tx * 4 + 2)       = __halves2half2(h[2], h[3]);
        *(__half2*)(rp + 64 + tx * 4)      = __halves2half2(l[0], l[1]);
        *(__half2*)(rp + 64 + tx * 4 + 2)  = __halves2half2(l[2], l[3]);
        *(__half2*)(rp + 128 + tx * 4)     = __halves2half2(h[4], h[5]);
        *(__half2*)(rp + 128 + tx * 4 + 2) = __halves2half2(h[6], h[7]);
        *(__half2*)(rp + 192 + tx * 4)     = __halves2half2(l[4], l[5]);
        *(__half2*)(rp + 192 + tx * 4 + 2) = __halves2half2(l[6], l[7]);
    }
}

DEV void dproj_body(const float* __restrict__ X, const float* __restrict__ Wd,
                    char* smraw, int bm, int bn) {
    __half* Xs = (__half*)smraw;                 // 128*24
    __half* Wt = Xs + 128 * 24;                  // 128*24
    __half* Ts = Wt + 128 * 24;                  // 128*136

    const int tid = threadIdx.x;
    const int lane = tid & 31, w = tid >> 5;
    const int g = lane >> 2, q = lane & 3;
    const int t15 = lane & 15;
    const int mw = (w & 3) * 32, nw = (w >> 2) * 64;

    const uint32 xs_b = smem_u32(Xs);
    const uint32 wt_b = smem_u32(Wt);
    const uint32 aAddr = xs_b + (uint32)((mw + t15) * 48 + ((lane >> 4) & 1) * 16);
    const uint32 bAddr = wt_b + (uint32)((nw + (lane & 7) + ((lane >> 4) & 1) * 8) * 48
                                         + ((lane >> 3) & 1) * 16);

    float4 acc[2][8];
#pragma unroll
    for (int i = 0; i < 2; i++)
#pragma unroll
        for (int j = 0; j < 8; j++) acc[i][j] = make_float4(0.f, 0.f, 0.f, 0.f);

    const int xm = tid >> 1, xk = (tid & 1) * 8;
    const int wk = (tid >> 5) * 2, wn = lane * 4;

    for (int kk = 0; kk < CDIM; kk += 16) {
        {
            const float* src = X + (size_t)(bm + xm) * CDIM + kk + xk;
            float4 v0 = *(const float4*)(src);
            float4 v1 = *(const float4*)(src + 4);
            __half* dst = Xs + xm * 24 + xk;
            *(__half2*)(dst)     = __floats2half2_rn(v0.x, v0.y);
            *(__half2*)(dst + 2) = __floats2half2_rn(v0.z, v0.w);
            *(__half2*)(dst + 4) = __floats2half2_rn(v1.x, v1.y);
            *(__half2*)(dst + 6) = __floats2half2_rn(v1.z, v1.w);
        }
        {
            const float* s0 = Wd + (size_t)(kk + wk) * CDIM + bn + wn;
            const float* s1 = s0 + CDIM;
            float4 a = *(const float4*)s0;
            float4 b = *(const float4*)s1;
            *(__half2*)(Wt + (wn + 0) * 24 + wk) = __floats2half2_rn(a.x, b.x);
            *(__half2*)(Wt + (wn + 1) * 24 + wk) = __floats2half2_rn(a.y, b.y);
            *(__half2*)(Wt + (wn + 2) * 24 + wk) = __floats2half2_rn(a.z, b.z);
            *(__half2*)(Wt + (wn + 3) * 24 + wk) = __floats2half2_rn(a.w, b.w);
        }
        __syncthreads();

        uint32 a0[2][4];
#pragma unroll
        for (int mt = 0; mt < 2; mt++)
            ldsm4(a0[mt][0], a0[mt][1], a0[mt][2], a0[mt][3],
                  aAddr + (uint32)(mt * 16 * 48));
#pragma unroll
        for (int nt2 = 0; nt2 < 4; nt2++) {
            uint32 b0, b1, b2, b3;
            ldsm4(b0, b1, b2, b3, bAddr + (uint32)(nt2 * 16 * 48));
#pragma unroll
            for (int mt = 0; mt < 2; mt++) {
                mma16(acc[mt][nt2 * 2],     a0[mt][0], a0[mt][1], a0[mt][2], a0[mt][3], b0, b1);
                mma16(acc[mt][nt2 * 2 + 1], a0[mt][0], a0[mt][1], a0[mt][2], a0[mt][3], b2, b3);
            }
        }
        __syncthreads();
    }

#pragma unroll
    for (int mt = 0; mt < 2; mt++) {
        int m0 = mw + mt * 16 + g;
#pragma unroll
        for (int nt = 0; nt < 8; nt++) {
            int n0 = nw + nt * 8 + 2 * q;
            Ts[(n0 + 0) * 136 + m0]     = __float2half_rn(acc[mt][nt].x);
            Ts[(n0 + 1) * 136 + m0]     = __float2half_rn(acc[mt][nt].y);
            Ts[(n0 + 0) * 136 + m0 + 8] = __float2half_rn(acc[mt][nt].z);
            Ts[(n0 + 1) * 136 + m0 + 8] = __float2half_rn(acc[mt][nt].w);
        }
    }
    __syncthreads();
    {
        int n = tid >> 1, half = tid & 1;
        int batch = bm >> 12, keyoff = bm & 4095;
        const uint4* src = (const uint4*)(Ts + n * 136 + half * 64);
        uint4* dst = (uint4*)(g_dT + ((size_t)batch * CDIM + bn + n) * HW
                              + keyoff + half * 64);
#pragma unroll
        for (int j = 0; j < 8; j++) dst[j] = src[j];
    }
}

__global__ void __launch_bounds__(256) fatproj(const float* __restrict__ X,
                                               const float* __restrict__ Wd) {
    extern __shared__ char smraw[];
    int bid = blockIdx.x;
    if (bid < 128) {
        proj_bc_body(X, smraw, bid * 128);
    } else {
        int idx = bid - 128;
        dproj_body(X, Wd, smraw, (idx & 127) * 128, (idx >> 7) * 128);
    }
}

// ---------- fused flash attention (round-9 structure, 2-term S) ----------
#define CS_OFF   0
#define BS_OFF   17408
#define BS_BYTES 34816
#define PS_OFF   87040
#define DS_OFF   104448
#define DS_BYTES 40960
#define STAT_OFF 186368
#define SMEM_FLASH (STAT_OFF + 2560)

__global__ void __launch_bounds__(512, 1) flash16(const float* __restrict__ x,
                                                  const float* __restrict__ gamma,
                                                  float* __restrict__ out) {
    extern __shared__ char sm[];
    __half* Cs = (__half*)(sm + CS_OFF);
    __half* Ps = (__half*)(sm + PS_OFF);
    float* m_part = (float*)(sm + STAT_OFF);        // [4][64]
    float* l_part = m_part + 256;                   // [4][64]
    float* sc_s   = l_part + 256;                   // [64]
    float* l_fin  = sc_s + 64;                      // [64]

    const uint32 smb  = smem_u32(sm);
    const uint32 cs_b = smb + CS_OFF;
    const uint32 bs_b = smb + BS_OFF;
    const uint32 ps_b = smb + PS_OFF;
    const uint32 ds_b = smb + DS_OFF;

    const int tid = threadIdx.x;
    const int wid = tid >> 5, lane = tid & 31;
    const int g = lane >> 2, q = lane & 3;
    const int qg = wid & 3;          // S: q-group rows qg*16..+15
    const int kq = wid >> 2;         // S: key-quarter (32k)
    const int qsub = wid & 1;        // PV: q-half (32 rows)
    const int fgrp = wid >> 1;       // PV: f-group (64 cols)
    const int t15 = lane & 15;
    const int qb = blockIdx.x * 64;
    const int bz = blockIdx.y;
    const int rowbase = bz * HW;

    // ---- load Cs once (ch|cl; cl kept resident but unused by S) ----
    {
        int r = tid >> 3, c = tid & 7;
        const uint4* src = (const uint4*)(g_bch + (size_t)(rowbase + qb + r) * 256 + 128);
        *(uint4*)(Cs + r * 136 + c * 8)       = src[c];
        *(uint4*)(Cs + r * 136 + (c + 8) * 8) = src[c + 8];
    }

    float4 oacc[16];
#pragma unroll
    for (int i = 0; i < 16; i++) oacc[i] = make_float4(0.f, 0.f, 0.f, 0.f);
    float mrun0 = -1e30f, mrun1 = -1e30f;
    float lrun0 = 0.f, lrun1 = 0.f;

    const uint32 aCh  = cs_b + (uint32)((qg * 16 + t15) * 272 + ((lane >> 4) & 1) * 16);
    const uint32 bBh0 = bs_b + (uint32)((kq * 32 + (lane & 7)) * 272 + ((lane >> 3) & 1) * 16);
    const uint32 psA  = ps_b + (uint32)((qsub * 32 + t15) * 272 + ((lane >> 4) & 1) * 16);
    const uint32 dRow = ds_b + (uint32)((fgrp * 64 + (lane & 7) + ((lane >> 4) & 1) * 8) * 80
                                        + ((lane >> 3) & 1) * 16);
    const int r0row = qg * 16 + g;            // S stat rows
    const int pvrow = qsub * 32 + g;          // PV rows

    const __half* dsrc = g_dT + ((size_t)(bz * CDIM + tid)) * HW;
    const uint32 dsDst = ds_b + (uint32)(tid * 80);
    const int bsR = tid >> 2, bsC = tid & 3;
    const uint32 bsDst = bs_b + (uint32)(bsR * 272 + bsC * 16);

    // prefetch Bs tile 0
    {
        const __half* src = g_bch + (size_t)(rowbase + bsR) * 256 + bsC * 8;
#pragma unroll
        for (int j = 0; j < 4; j++) CP16(bsDst + j * 64, src + j * 32);
        CP_COMMIT();
    }

    for (int t = 0; t < 32; t++) {
        const int kt = t * 128;
        const uint32 bsBuf = (uint32)((t & 1) * BS_BYTES);

        // issue Ds chunks 0,1
#pragma unroll
        for (int c = 0; c < 2; c++) {
            const __half* src = dsrc + kt + c * 32;
            uint32 dst = dsDst + (uint32)(c * DS_BYTES);
#pragma unroll
            for (int j = 0; j < 4; j++) CP16(dst + j * 16, src + j * 8);
            CP_COMMIT();
        }
        CP_WAIT2();          // Bs(t) done
        __syncthreads();

        // ---- S phase: 2-term fp16 (ch*bh + ch*bl), prefetched fragments ----
        float4 sacc[4];
#pragma unroll
        for (int i = 0; i < 4; i++) sacc[i] = make_float4(0.f, 0.f, 0.f, 0.f);
        const uint32 bB = bBh0 + bsBuf;
        {
            uint32 ah[4], nah[4];
            uint32 bh0, bh1, bl0, bl1, nbh0, nbh1, nbl0, nbl1;
            ldsm4(ah[0], ah[1], ah[2], ah[3], aCh);
            ldsm2(bh0, bh1, bB);
            ldsm2(bl0, bl1, bB + 128);
#pragma unroll
            for (int ec = 0; ec < 4; ec++) {
                if (ec < 3)
                    ldsm4(nah[0], nah[1], nah[2], nah[3], aCh + (ec + 1) * 32);
#pragma unroll
                for (int nt = 0; nt < 4; nt++) {
                    if (nt < 3) {
                        ldsm2(nbh0, nbh1, bB + (nt + 1) * 2176 + ec * 32);
                        ldsm2(nbl0, nbl1, bB + (nt + 1) * 2176 + ec * 32 + 128);
                    } else if (ec < 3) {
                        ldsm2(nbh0, nbh1, bB + (ec + 1) * 32);
                        ldsm2(nbl0, nbl1, bB + (ec + 1) * 32 + 128);
                    }
                    mma16(sacc[nt], ah[0], ah[1], ah[2], ah[3], bh0, bh1);
                    mma16(sacc[nt], ah[0], ah[1], ah[2], ah[3], bl0, bl1);
                    bh0 = nbh0; bh1 = nbh1; bl0 = nbl0; bl1 = nbl1;
                }
#pragma unroll
                for (int j = 0; j < 4; j++) ah[j] = nah[j];
            }
        }

        // ---- softmax partials ----
        float mx0 = sacc[0].x, mx1 = sacc[0].z;
#pragma unroll
        for (int nt = 0; nt < 4; nt++) {
            mx0 = fmaxf(mx0, fmaxf(sacc[nt].x, sacc[nt].y));
            mx1 = fmaxf(mx1, fmaxf(sacc[nt].z, sacc[nt].w));
        }
        mx0 = fmaxf(mx0, __shfl_xor_sync(0xffffffffu, mx0, 1));
        mx0 = fmaxf(mx0, __shfl_xor_sync(0xffffffffu, mx0, 2));
        mx1 = fmaxf(mx1, __shfl_xor_sync(0xffffffffu, mx1, 1));
        mx1 = fmaxf(mx1, __shfl_xor_sync(0xffffffffu, mx1, 2));
        if (q == 0) {
            m_part[kq * 64 + r0row]     = mx0;
            m_part[kq * 64 + r0row + 8] = mx1;
        }
        __syncthreads();

        float mt0 = fmaxf(fmaxf(m_part[r0row], m_part[64 + r0row]),
                          fmaxf(m_part[128 + r0row], m_part[192 + r0row]));
        float mt1 = fmaxf(fmaxf(m_part[r0row + 8], m_part[64 + r0row + 8]),
                          fmaxf(m_part[128 + r0row + 8], m_part[192 + r0row + 8]));
        float mn0 = fmaxf(mrun0, mt0), mn1 = fmaxf(mrun1, mt1);
        float sc0 = __expf(mrun0 - mn0), sc1 = __expf(mrun1 - mn1);
        mrun0 = mn0; mrun1 = mn1;

        float ls0 = 0.f, ls1 = 0.f;
#pragma unroll
        for (int nt = 0; nt < 4; nt++) {
            float px = __expf(sacc[nt].x - mn0), py = __expf(sacc[nt].y - mn0);
            float pz = __expf(sacc[nt].z - mn1), pw = __expf(sacc[nt].w - mn1);
            ls0 += px + py; ls1 += pz + pw;
            int col = kq * 32 + nt * 8 + 2 * q;
            *(__half2*)(Ps + r0row * 136 + col)       = __floats2half2_rn(px, py);
            *(__half2*)(Ps + (r0row + 8) * 136 + col) = __floats2half2_rn(pz, pw);
        }
        ls0 += __shfl_xor_sync(0xffffffffu, ls0, 1);
        ls0 += __shfl_xor_sync(0xffffffffu, ls0, 2);
        ls1 += __shfl_xor_sync(0xffffffffu, ls1, 1);
        ls1 += __shfl_xor_sync(0xffffffffu, ls1, 2);
        if (q == 0) {
            l_part[kq * 64 + r0row]     = ls0;
            l_part[kq * 64 + r0row + 8] = ls1;
            if (kq == 0) { sc_s[r0row] = sc0; sc_s[r0row + 8] = sc1; }
        }

        // prefetch next Bs tile (empty group on last tile keeps counts exact)
        if (t < 31) {
            const __half* src = g_bch + (size_t)(rowbase + kt + 128 + bsR) * 256 + bsC * 8;
            uint32 dst = bsDst + (uint32)(((t + 1) & 1) * BS_BYTES);
#pragma unroll
            for (int j = 0; j < 4; j++) CP16(dst + j * 64, src + j * 32);
        }
        CP_COMMIT();
        __syncthreads();

        // ---- rescale O only when max moved ----
        {
            float s0 = sc_s[pvrow], s1 = sc_s[pvrow + 8];
            float s2 = sc_s[pvrow + 16], s3 = sc_s[pvrow + 24];
            bool noscale = __all_sync(0xffffffffu,
                (s0 == 1.f) && (s1 == 1.f) && (s2 == 1.f) && (s3 == 1.f));
            if (!noscale) {
#pragma unroll
                for (int nt = 0; nt < 8; nt++) {
                    oacc[nt].x *= s0; oacc[nt].y *= s0;
                    oacc[nt].z *= s1; oacc[nt].w *= s1;
                    oacc[8 + nt].x *= s2; oacc[8 + nt].y *= s2;
                    oacc[8 + nt].z *= s3; oacc[8 + nt].w *= s3;
                }
            }
        }
        lrun0 = lrun0 * sc0 + (l_part[r0row] + l_part[64 + r0row]
                             + l_part[128 + r0row] + l_part[192 + r0row]);
        lrun1 = lrun1 * sc1 + (l_part[r0row + 8] + l_part[64 + r0row + 8]
                             + l_part[128 + r0row + 8] + l_part[192 + r0row + 8]);

        // ---- PV: 4 chunks of 32 keys, cp.async pipelined + fragment prefetch ----
#pragma unroll
        for (int c = 0; c < 4; c++) {
            if (c == 0) CP_WAIT2();
            else if (c == 1) CP_WAIT2();
            else if (c == 2) CP_WAIT1();
            else CP_WAIT0();
            __syncthreads();
            const uint32 dBuf = (uint32)((c & 1) * DS_BYTES);
            uint32 pa[4], pb[4], npa[4], npb[4], bf[4], nbf[4];
            ldsm4(pa[0], pa[1], pa[2], pa[3], psA + (uint32)(c * 64));
            ldsm4(pb[0], pb[1], pb[2], pb[3], psA + 16 * 272 + (uint32)(c * 64));
            ldsm4(bf[0], bf[1], bf[2], bf[3], dRow + dBuf);
#pragma unroll
            for (int kcl = 0; kcl < 2; kcl++) {
#pragma unroll
                for (int ftp = 0; ftp < 4; ftp++) {
                    if (ftp < 3) {
                        ldsm4(nbf[0], nbf[1], nbf[2], nbf[3],
                              dRow + dBuf + (uint32)((ftp + 1) * 1280 + kcl * 32));
                    } else if (kcl == 0) {
                        ldsm4(npa[0], npa[1], npa[2], npa[3], psA + (uint32)(c * 64 + 32));
                        ldsm4(npb[0], npb[1], npb[2], npb[3],
                              psA + 16 * 272 + (uint32)(c * 64 + 32));
                        ldsm4(nbf[0], nbf[1], nbf[2], nbf[3], dRow + dBuf + 32);
                    }
                    mma16(oacc[ftp * 2],     pa[0], pa[1], pa[2], pa[3], bf[0], bf[1]);
                    mma16(oacc[ftp * 2 + 1], pa[0], pa[1], pa[2], pa[3], bf[2], bf[3]);
                    mma16(oacc[8 + ftp * 2],     pb[0], pb[1], pb[2], pb[3], bf[0], bf[1]);
                    mma16(oacc[8 + ftp * 2 + 1], pb[0], pb[1], pb[2], pb[3], bf[2], bf[3]);
#pragma unroll
                    for (int j = 0; j < 4; j++) bf[j] = nbf[j];
                    if (ftp == 3 && kcl == 0) {
#pragma unroll
                        for (int j = 0; j < 4; j++) { pa[j] = npa[j]; pb[j] = npb[j]; }
                    }
                }
            }
            __syncthreads();
            if (c < 2) {
                const __half* src = dsrc + kt + (c + 2) * 32;
                uint32 dst = dsDst + dBuf;
#pragma unroll
                for (int j = 0; j < 4; j++) CP16(dst + j * 16, src + j * 8);
                CP_COMMIT();
            }
        }
    }

    // ---- publish final l, epilogue ----
    if (kq == 0 && q == 0) {
        l_fin[r0row]     = lrun0;
        l_fin[r0row + 8] = lrun1;
    }
    __syncthreads();
    {
        float li0 = 1.0f / l_fin[pvrow],      li1 = 1.0f / l_fin[pvrow + 8];
        float li2 = 1.0f / l_fin[pvrow + 16], li3 = 1.0f / l_fin[pvrow + 24];
        float gam = *gamma;
#pragma unroll
        for (int sub = 0; sub < 2; sub++) {
            size_t row0 = (size_t)(rowbase + qb + pvrow + sub * 16);
            size_t row1 = row0 + 8;
            float a0 = sub ? li2 : li0, a1 = sub ? li3 : li1;
#pragma unroll
            for (int nt = 0; nt < 8; nt++) {
                int col = fgrp * 64 + nt * 8 + 2 * q;
                float4 o = oacc[sub * 8 + nt];
                float2 x0 = *(const float2*)(x + row0 * CDIM + col);
                float2 x1 = *(const float2*)(x + row1 * CDIM + col);
                *(float2*)(out + row0 * CDIM + col) =
                    make_float2(gam * o.x * a0 + x0.x, gam * o.y * a0 + x0.y);
                *(float2*)(out + row1 * CDIM + col) =
                    make_float2(gam * o.z * a1 + x1.x, gam * o.w * a1 + x1.y);
            }
        }
    }
}

// ---------- launch ----------
extern "C" void kernel_launch(void* const* d_in, const int* in_sizes, int n_in,
                              void* d_out, int out_size) {
    const float* x     = (const float*)d_in[0];
    const float* Wb    = (const float*)d_in[1];
    const float* Wc    = (const float*)d_in[2];
    const float* Wd    = (const float*)d_in[3];
    const float* gamma = (const float*)d_in[4];
    float* out = (float*)d_out;

    pack_wbc<<<128, 256>>>(Wb, Wc);

    cudaFuncSetAttribute(fatproj, cudaFuncAttributeMaxDynamicSharedMemorySize, FP_SMEM);
    fatproj<<<640, 256, FP_SMEM>>>(x, Wd);

    cudaFuncSetAttribute(flash16, cudaFuncAttributeMaxDynamicSharedMemorySize,
                         (int)SMEM_FLASH);
    flash16<<<dim3(HW / 64, BATCH), 512, SMEM_FLASH>>>(x, gamma, out);
}